// round 7
// baseline (speedup 1.0000x reference)
#include <cuda_runtime.h>

#define VOCAB 50257
#define NT 512
#define NFULL 98                 // j = 0..97 always in-bounds (97*512+511 = 50175 < VOCAB)
#define EPT 99
#define T1 6.0f                  // capture threshold; E[count(g>=6)] ~ 205, k-th ~ 7.4
#define CAP 768                  // candidate buffer capacity (mean 205, sigma ~14)
#define WMAX 128                 // fallback bisection window
#define GS_BYTES ((VOCAB * 4 + 15) & ~15)   // 201040

#define NEG_SENT -3.402823466e38f

struct Scratch {
    int      sredi[17];
    float    sredf[17];
    float    cbuf[CAP];
    float    wbuf[WMAX + 32];
    int      ccnt;
    int      wcnt;
    float    thrslot;
};

#define SMEM_TOTAL (GS_BYTES + (int)sizeof(Scratch))

// ---- order-preserving float <-> u32 key (fallback path only) ----
__device__ __forceinline__ unsigned fkey(float f) {
    unsigned b = __float_as_uint(f);
    unsigned m = (unsigned)(((int)b) >> 31) | 0x80000000u;
    return b ^ m;
}
__device__ __forceinline__ float keyf(unsigned k) {
    unsigned m = (~(unsigned)(((int)k) >> 31)) | 0x80000000u;
    return __uint_as_float(k ^ m);
}

// ---- block reductions (512 threads = 16 warps) ----
__device__ __forceinline__ int blockSumI(int v, int* s) {
    #pragma unroll
    for (int o = 16; o; o >>= 1) v += __shfl_xor_sync(0xffffffffu, v, o);
    int wid = threadIdx.x >> 5, lane = threadIdx.x & 31;
    if (lane == 0) s[wid] = v;
    __syncthreads();
    if (wid == 0) {
        int x = (lane < (NT / 32)) ? s[lane] : 0;
        #pragma unroll
        for (int o = 8; o; o >>= 1) x += __shfl_xor_sync(0xffffffffu, x, o);
        if (lane == 0) s[16] = x;
    }
    __syncthreads();
    int r = s[16];
    __syncthreads();
    return r;
}

__device__ __forceinline__ float blockSumF(float v, float* s) {
    #pragma unroll
    for (int o = 16; o; o >>= 1) v += __shfl_xor_sync(0xffffffffu, v, o);
    int wid = threadIdx.x >> 5, lane = threadIdx.x & 31;
    if (lane == 0) s[wid] = v;
    __syncthreads();
    if (wid == 0) {
        float x = (lane < (NT / 32)) ? s[lane] : 0.0f;
        #pragma unroll
        for (int o = 8; o; o >>= 1) x += __shfl_xor_sync(0xffffffffu, x, o);
        if (lane == 0) s[16] = x;
    }
    __syncthreads();
    float r = s[16];
    __syncthreads();
    return r;
}

// noise = -log(-log(u + EPS) + EPS), with an exact log1p polynomial for u near 1
// (u -> 1 is exactly the top-k-defining region; MUFU LG2's absolute error there
//  would otherwise amplify to ~1e-2 in the noise).
__device__ __forceinline__ float gumbel_noise(float uu) {
    float vlog = -__logf(uu + 1e-10f);
    float d = uu - 1.0f;                         // exact (Sterbenz) for uu in [0.5, 2)
    float p = __fmaf_rn(-0.25f, d, 0.33333333f); // log1p(d) = d*(1 - d/2 + d^2/3 - d^3/4)
    p = __fmaf_rn(p, d, -0.5f);
    p = __fmaf_rn(p, d, 1.0f);
    float vpoly = -(d * p);
    float v = (uu > 0.99f) ? vpoly : vlog;
    return -__logf(v + 1e-10f);
}

__global__ void __launch_bounds__(NT, 1)
gumbel_sampler_kernel(const float* __restrict__ logits,
                      const float* __restrict__ uin,
                      const int* __restrict__ kp,
                      float* __restrict__ out)
{
    extern __shared__ unsigned char smem_raw[];
    float*   gs = (float*)smem_raw;
    Scratch* sc = (Scratch*)(smem_raw + GS_BYTES);

    const int row = blockIdx.x;
    const int tid = threadIdx.x;
    const float* __restrict__ lrow = logits + (size_t)row * VOCAB;
    const float* __restrict__ urow = uin    + (size_t)row * VOCAB;
    float* __restrict__ orow = out + (size_t)row * VOCAB;
    const int k = *kp;

    if (tid == 0) sc->ccnt = 0;
    __syncthreads();

    float lreg[EPT];

    // ------- P1: load + gumbel; g -> smem; logits -> registers; capture g>=T1 ----
    // FULL unroll is load-bearing: lreg[] must stay in registers (partial unroll
    // demotes it to local memory -> 2x regression, see R3 post-mortem).
    #pragma unroll
    for (int j = 0; j < NFULL; ++j) {
        int idx = tid + j * NT;
        float l = __ldcs(lrow + idx);
        float g = l + gumbel_noise(__ldcs(urow + idx));
        lreg[j] = l;
        gs[idx] = g;
        if (g >= T1) {
            int p = atomicAdd(&sc->ccnt, 1);
            if (p < CAP) sc->cbuf[p] = g;
        }
    }
    {
        int idx = tid + NFULL * NT;
        if (idx < VOCAB) {
            float l = __ldcs(lrow + idx);
            float g = l + gumbel_noise(__ldcs(urow + idx));
            lreg[NFULL] = l;
            gs[idx] = g;
            if (g >= T1) {
                int p = atomicAdd(&sc->ccnt, 1);
                if (p < CAP) sc->cbuf[p] = g;
            }
        }
    }
    __syncthreads();

    // ------- P2: exact k-th largest directly from the candidate buffer -------
    // count(>=T1) = m >= k  =>  k-th largest overall is the k-th largest of cbuf.
    int m = sc->ccnt;
    float thr;

    if (m >= k && m <= 512) {
        if (tid < m) {
            float vt = sc->cbuf[tid];
            int gt = 0, ge = 0;
            for (int j = 0; j < m; ++j) {
                float vj = sc->cbuf[j];         // broadcast LDS
                gt += (vj >  vt);
                ge += (vj >= vt);
            }
            if (gt < k && k <= ge) sc->thrslot = vt;
        }
        __syncthreads();
        thr = sc->thrslot;
    } else {
        // fallback (never expected): full bisection over all of gs via order keys
        unsigned lo = 0u, hi = 0xFFFFFFFFu;
        int c_lo = VOCAB, c_hi = 0;
        while ((hi - lo) > 1u && (c_lo - c_hi) > WMAX) {
            unsigned mid = lo + ((hi - lo) >> 1);
            int c = 0;
            for (int i = tid; i < VOCAB; i += NT) c += (fkey(gs[i]) >= mid);
            c = blockSumI(c, sc->sredi);
            if (c >= k) { lo = mid; c_lo = c; }
            else        { hi = mid; c_hi = c; }
        }
        if ((hi - lo) <= 1u) {
            thr = keyf(lo);
        } else {
            if (tid == 0) sc->wcnt = 0;
            __syncthreads();
            for (int i = tid; i < VOCAB; i += NT) {
                float v = gs[i];
                unsigned kk = fkey(v);
                if (kk >= lo && kk < hi) {
                    int p = atomicAdd(&sc->wcnt, 1);
                    if (p < WMAX + 32) sc->wbuf[p] = v;
                }
            }
            __syncthreads();
            int w = sc->wcnt; if (w > WMAX + 32) w = WMAX + 32;
            int need = k - c_hi;
            if (tid < w) {
                float vt = sc->wbuf[tid];
                int gt = 0, ge = 0;
                for (int j = 0; j < w; ++j) {
                    float vj = sc->wbuf[j];
                    gt += (vj >  vt);
                    ge += (vj >= vt);
                }
                if (gt < need && need <= ge) sc->thrslot = vt;
            }
            __syncthreads();
            thr = sc->thrslot;
        }
    }

    // ------- P3: fused mask + exp + sum (single pass; no max subtraction) -------
    // masked = l * sigmoid(g - thr) is bounded by |l| <= ~5.5 for N(0,1) inputs,
    // so exp(masked) is in [e^-6, e^6]: no fp32 overflow/underflow possible,
    // and softmax without max-shift is exact.
    float lsum = 0.0f;
    #pragma unroll
    for (int j = 0; j < NFULL; ++j) {
        int idx = tid + j * NT;
        float g = gs[idx];
        float s = __fdividef(1.0f, 1.0f + __expf(thr - g));
        float e = __expf(lreg[j] * s);
        lreg[j] = e;
        lsum += e;
    }
    {
        int idx = tid + NFULL * NT;
        if (idx < VOCAB) {
            float g = gs[idx];
            float s = __fdividef(1.0f, 1.0f + __expf(thr - g));
            float e = __expf(lreg[NFULL] * s);
            lreg[NFULL] = e;
            lsum += e;
        }
    }
    float S = blockSumF(lsum, sc->sredf);
    float inv = __fdividef(1.0f, S);

    // ------- L2 prefetch of the next wave's row, just before the store pass -------
    // Short residency window (~store duration) -> prefetched lines survive in L2
    // until the next CTA on this SM reads them in its P1.
    {
        int pf = row + 148;
        if (pf < (int)gridDim.x) {
            const float* pl = logits + (size_t)pf * VOCAB;
            const float* pu = uin    + (size_t)pf * VOCAB;
            #pragma unroll 1
            for (int i = tid * 32; i < VOCAB; i += NT * 32) {
                asm volatile("prefetch.global.L2 [%0];" :: "l"(pl + i));
                asm volatile("prefetch.global.L2 [%0];" :: "l"(pu + i));
            }
        }
    }

    // ------- Pass C: scaled streaming store straight from registers -------
    #pragma unroll
    for (int j = 0; j < NFULL; ++j) {
        int idx = tid + j * NT;
        __stcs(orow + idx, lreg[j] * inv);
    }
    {
        int idx = tid + NFULL * NT;
        if (idx < VOCAB) __stcs(orow + idx, lreg[NFULL] * inv);
    }
}

extern "C" void kernel_launch(void* const* d_in, const int* in_sizes, int n_in,
                              void* d_out, int out_size)
{
    const float* logits = (const float*)d_in[0];
    const float* u      = (const float*)d_in[1];
    const int*   kp     = (const int*)d_in[2];
    float* out = (float*)d_out;

    int B = out_size / VOCAB;

    cudaFuncSetAttribute(gumbel_sampler_kernel,
                         cudaFuncAttributeMaxDynamicSharedMemorySize, SMEM_TOTAL);
    gumbel_sampler_kernel<<<B, NT, SMEM_TOTAL>>>(logits, u, kp, out);
}

// round 8
// speedup vs baseline: 1.1114x; 1.1114x over previous
#include <cuda_runtime.h>

#define VOCAB 50257
#define NT 512
#define NFULL 98                 // j = 0..97 always in-bounds (97*512+511 = 50175 < VOCAB)
#define EPT 99
#define T1 6.0f                  // capture threshold; E[count(g>=6)] ~ 205, k-th ~ 7.4
#define CAP 768                  // candidate buffer capacity (mean 205, sigma ~14)
#define WMAX 128                 // fallback bisection window
#define GS_BYTES ((VOCAB * 4 + 15) & ~15)   // 201040

#define NEG_SENT -3.402823466e38f

struct Scratch {
    int      sredi[17];
    float    sredf[17];
    float    cbuf[CAP];
    float    wbuf[WMAX + 32];
    int      ccnt;
    int      wcnt;
    float    thrslot;
};

#define SMEM_TOTAL (GS_BYTES + (int)sizeof(Scratch))

// ---- order-preserving float <-> u32 key (fallback path only) ----
__device__ __forceinline__ unsigned fkey(float f) {
    unsigned b = __float_as_uint(f);
    unsigned m = (unsigned)(((int)b) >> 31) | 0x80000000u;
    return b ^ m;
}
__device__ __forceinline__ float keyf(unsigned k) {
    unsigned m = (~(unsigned)(((int)k) >> 31)) | 0x80000000u;
    return __uint_as_float(k ^ m);
}

// ---- block reductions (512 threads = 16 warps) ----
__device__ __forceinline__ int blockSumI(int v, int* s) {
    #pragma unroll
    for (int o = 16; o; o >>= 1) v += __shfl_xor_sync(0xffffffffu, v, o);
    int wid = threadIdx.x >> 5, lane = threadIdx.x & 31;
    if (lane == 0) s[wid] = v;
    __syncthreads();
    if (wid == 0) {
        int x = (lane < (NT / 32)) ? s[lane] : 0;
        #pragma unroll
        for (int o = 8; o; o >>= 1) x += __shfl_xor_sync(0xffffffffu, x, o);
        if (lane == 0) s[16] = x;
    }
    __syncthreads();
    int r = s[16];
    __syncthreads();
    return r;
}

__device__ __forceinline__ float blockSumF(float v, float* s) {
    #pragma unroll
    for (int o = 16; o; o >>= 1) v += __shfl_xor_sync(0xffffffffu, v, o);
    int wid = threadIdx.x >> 5, lane = threadIdx.x & 31;
    if (lane == 0) s[wid] = v;
    __syncthreads();
    if (wid == 0) {
        float x = (lane < (NT / 32)) ? s[lane] : 0.0f;
        #pragma unroll
        for (int o = 8; o; o >>= 1) x += __shfl_xor_sync(0xffffffffu, x, o);
        if (lane == 0) s[16] = x;
    }
    __syncthreads();
    float r = s[16];
    __syncthreads();
    return r;
}

// noise = -log(-log(u + EPS) + EPS), with an exact log1p polynomial for u near 1
// (u -> 1 is exactly the top-k-defining region; MUFU LG2's absolute error there
//  would otherwise amplify to ~1e-2 in the noise).
__device__ __forceinline__ float gumbel_noise(float uu) {
    float vlog = -__logf(uu + 1e-10f);
    float d = uu - 1.0f;                         // exact (Sterbenz) for uu in [0.5, 2)
    float p = __fmaf_rn(-0.25f, d, 0.33333333f); // log1p(d) = d*(1 - d/2 + d^2/3 - d^3/4)
    p = __fmaf_rn(p, d, -0.5f);
    p = __fmaf_rn(p, d, 1.0f);
    float vpoly = -(d * p);
    float v = (uu > 0.99f) ? vpoly : vlog;
    return -__logf(v + 1e-10f);
}

__global__ void __launch_bounds__(NT, 1)
gumbel_sampler_kernel(const float* __restrict__ logits,
                      const float* __restrict__ uin,
                      const int* __restrict__ kp,
                      float* __restrict__ out)
{
    extern __shared__ unsigned char smem_raw[];
    float*   gs = (float*)smem_raw;
    Scratch* sc = (Scratch*)(smem_raw + GS_BYTES);

    const int row = blockIdx.x;
    const int tid = threadIdx.x;
    const float* __restrict__ lrow = logits + (size_t)row * VOCAB;
    const float* __restrict__ urow = uin    + (size_t)row * VOCAB;
    float* __restrict__ orow = out + (size_t)row * VOCAB;
    const int k = *kp;

    if (tid == 0) sc->ccnt = 0;
    __syncthreads();

    float lreg[EPT];

    // ------- P1: load + gumbel; g -> smem; logits -> registers; capture g>=T1 ----
    // FULL unroll is load-bearing: lreg[] must stay in registers (partial unroll
    // demotes it to local memory -> 2x regression, see R3 post-mortem).
    #pragma unroll
    for (int j = 0; j < NFULL; ++j) {
        int idx = tid + j * NT;
        float l = __ldcs(lrow + idx);
        float g = l + gumbel_noise(__ldcs(urow + idx));
        lreg[j] = l;
        gs[idx] = g;
        if (g >= T1) {
            int p = atomicAdd(&sc->ccnt, 1);
            if (p < CAP) sc->cbuf[p] = g;
        }
    }
    {
        int idx = tid + NFULL * NT;
        if (idx < VOCAB) {
            float l = __ldcs(lrow + idx);
            float g = l + gumbel_noise(__ldcs(urow + idx));
            lreg[NFULL] = l;
            gs[idx] = g;
            if (g >= T1) {
                int p = atomicAdd(&sc->ccnt, 1);
                if (p < CAP) sc->cbuf[p] = g;
            }
        }
    }
    __syncthreads();

    // ------- L2 prefetch of the next wave's row, EARLY (post-P1) -------
    // The whole P2+P3 window (~25us) lets the prefetch drain from DRAM into L2
    // before the next CTA on this SM reads these lines in its P1. The late
    // (pre-store) placement regressed 383->400us in R7: not enough drain time.
    {
        int pf = row + 148;
        if (pf < (int)gridDim.x) {
            const float* pl = logits + (size_t)pf * VOCAB;
            const float* pu = uin    + (size_t)pf * VOCAB;
            #pragma unroll 1
            for (int i = tid * 32; i < VOCAB; i += NT * 32) {
                asm volatile("prefetch.global.L2 [%0];" :: "l"(pl + i));
                asm volatile("prefetch.global.L2 [%0];" :: "l"(pu + i));
            }
        }
    }

    // ------- P2: exact k-th largest directly from the candidate buffer -------
    // count(>=T1) = m >= k  =>  k-th largest overall is the k-th largest of cbuf.
    int m = sc->ccnt;
    float thr;

    if (m >= k && m <= 512) {
        if (tid < m) {
            float vt = sc->cbuf[tid];
            int gt = 0, ge = 0;
            for (int j = 0; j < m; ++j) {
                float vj = sc->cbuf[j];         // broadcast LDS
                gt += (vj >  vt);
                ge += (vj >= vt);
            }
            if (gt < k && k <= ge) sc->thrslot = vt;
        }
        __syncthreads();
        thr = sc->thrslot;
    } else {
        // fallback (never expected): full bisection over all of gs via order keys
        unsigned lo = 0u, hi = 0xFFFFFFFFu;
        int c_lo = VOCAB, c_hi = 0;
        while ((hi - lo) > 1u && (c_lo - c_hi) > WMAX) {
            unsigned mid = lo + ((hi - lo) >> 1);
            int c = 0;
            for (int i = tid; i < VOCAB; i += NT) c += (fkey(gs[i]) >= mid);
            c = blockSumI(c, sc->sredi);
            if (c >= k) { lo = mid; c_lo = c; }
            else        { hi = mid; c_hi = c; }
        }
        if ((hi - lo) <= 1u) {
            thr = keyf(lo);
        } else {
            if (tid == 0) sc->wcnt = 0;
            __syncthreads();
            for (int i = tid; i < VOCAB; i += NT) {
                float v = gs[i];
                unsigned kk = fkey(v);
                if (kk >= lo && kk < hi) {
                    int p = atomicAdd(&sc->wcnt, 1);
                    if (p < WMAX + 32) sc->wbuf[p] = v;
                }
            }
            __syncthreads();
            int w = sc->wcnt; if (w > WMAX + 32) w = WMAX + 32;
            int need = k - c_hi;
            if (tid < w) {
                float vt = sc->wbuf[tid];
                int gt = 0, ge = 0;
                for (int j = 0; j < w; ++j) {
                    float vj = sc->wbuf[j];
                    gt += (vj >  vt);
                    ge += (vj >= vt);
                }
                if (gt < need && need <= ge) sc->thrslot = vt;
            }
            __syncthreads();
            thr = sc->thrslot;
        }
    }

    // ------- P3: fused mask + exp + sum (single pass; no max subtraction) -------
    // masked = l * sigmoid(g - thr) is bounded by |l| <= ~5.5 for N(0,1) inputs,
    // so exp(masked) is in [e^-6, e^6]: no fp32 overflow/underflow possible,
    // and softmax without max-shift is exact.
    float lsum = 0.0f;
    #pragma unroll
    for (int j = 0; j < NFULL; ++j) {
        int idx = tid + j * NT;
        float g = gs[idx];
        float s = __fdividef(1.0f, 1.0f + __expf(thr - g));
        float e = __expf(lreg[j] * s);
        lreg[j] = e;
        lsum += e;
    }
    {
        int idx = tid + NFULL * NT;
        if (idx < VOCAB) {
            float g = gs[idx];
            float s = __fdividef(1.0f, 1.0f + __expf(thr - g));
            float e = __expf(lreg[NFULL] * s);
            lreg[NFULL] = e;
            lsum += e;
        }
    }
    float S = blockSumF(lsum, sc->sredf);
    float inv = __fdividef(1.0f, S);

    // ------- Pass C: scaled streaming store straight from registers -------
    #pragma unroll
    for (int j = 0; j < NFULL; ++j) {
        int idx = tid + j * NT;
        __stcs(orow + idx, lreg[j] * inv);
    }
    {
        int idx = tid + NFULL * NT;
        if (idx < VOCAB) __stcs(orow + idx, lreg[NFULL] * inv);
    }
}

extern "C" void kernel_launch(void* const* d_in, const int* in_sizes, int n_in,
                              void* d_out, int out_size)
{
    const float* logits = (const float*)d_in[0];
    const float* u      = (const float*)d_in[1];
    const int*   kp     = (const int*)d_in[2];
    float* out = (float*)d_out;

    int B = out_size / VOCAB;

    cudaFuncSetAttribute(gumbel_sampler_kernel,
                         cudaFuncAttributeMaxDynamicSharedMemorySize, SMEM_TOTAL);
    gumbel_sampler_kernel<<<B, NT, SMEM_TOTAL>>>(logits, u, kp, out);
}

// round 9
// speedup vs baseline: 1.1784x; 1.0603x over previous
#include <cuda_runtime.h>

#define VOCAB 50257
#define NT 512
#define NPAIR 25128              // float2 pairs per row after 1-element peel
#define NPJ 49                   // full pair iterations: 49*512 = 25088
#define TAILP 40                 // tail pairs: 25128 - 25088
#define T1 6.0f                  // capture threshold; E[count(g>=6)] ~ 205, k-th ~ 7.4
#define CAP 768                  // candidate buffer capacity (mean 205, sigma ~14)
#define WMAX 128                 // fallback bisection window
// pairs [0..25127] then scalar slot at float index 50256 -> contiguous 50257 floats
#define GS_BYTES ((NPAIR * 8 + 4 + 15) & ~15)

#define NEG_SENT -3.402823466e38f

struct Scratch {
    int      sredi[17];
    float    sredf[17];
    float    cbuf[CAP];
    float    wbuf[WMAX + 32];
    int      ccnt;
    int      wcnt;
    float    thrslot;
    float    lscalar;            // logit of the peeled scalar element
    float    escalar;            // its exp value
};

#define SMEM_TOTAL (GS_BYTES + (int)sizeof(Scratch))

// ---- order-preserving float <-> u32 key (fallback path only) ----
__device__ __forceinline__ unsigned fkey(float f) {
    unsigned b = __float_as_uint(f);
    unsigned m = (unsigned)(((int)b) >> 31) | 0x80000000u;
    return b ^ m;
}
__device__ __forceinline__ float keyf(unsigned k) {
    unsigned m = (~(unsigned)(((int)k) >> 31)) | 0x80000000u;
    return __uint_as_float(k ^ m);
}

// ---- block reductions (512 threads = 16 warps) ----
__device__ __forceinline__ int blockSumI(int v, int* s) {
    #pragma unroll
    for (int o = 16; o; o >>= 1) v += __shfl_xor_sync(0xffffffffu, v, o);
    int wid = threadIdx.x >> 5, lane = threadIdx.x & 31;
    if (lane == 0) s[wid] = v;
    __syncthreads();
    if (wid == 0) {
        int x = (lane < (NT / 32)) ? s[lane] : 0;
        #pragma unroll
        for (int o = 8; o; o >>= 1) x += __shfl_xor_sync(0xffffffffu, x, o);
        if (lane == 0) s[16] = x;
    }
    __syncthreads();
    int r = s[16];
    __syncthreads();
    return r;
}

__device__ __forceinline__ float blockSumF(float v, float* s) {
    #pragma unroll
    for (int o = 16; o; o >>= 1) v += __shfl_xor_sync(0xffffffffu, v, o);
    int wid = threadIdx.x >> 5, lane = threadIdx.x & 31;
    if (lane == 0) s[wid] = v;
    __syncthreads();
    if (wid == 0) {
        float x = (lane < (NT / 32)) ? s[lane] : 0.0f;
        #pragma unroll
        for (int o = 8; o; o >>= 1) x += __shfl_xor_sync(0xffffffffu, x, o);
        if (lane == 0) s[16] = x;
    }
    __syncthreads();
    float r = s[16];
    __syncthreads();
    return r;
}

// noise = -log(-log(u + EPS) + EPS), with an exact log1p polynomial for u near 1
// (u -> 1 is exactly the top-k-defining region; MUFU LG2's absolute error there
//  would otherwise amplify to ~1e-2 in the noise).
__device__ __forceinline__ float gumbel_noise(float uu) {
    float vlog = -__logf(uu + 1e-10f);
    float d = uu - 1.0f;                         // exact (Sterbenz) for uu in [0.5, 2)
    float p = __fmaf_rn(-0.25f, d, 0.33333333f); // log1p(d) = d*(1 - d/2 + d^2/3 - d^3/4)
    p = __fmaf_rn(p, d, -0.5f);
    p = __fmaf_rn(p, d, 1.0f);
    float vpoly = -(d * p);
    float v = (uu > 0.99f) ? vpoly : vlog;
    return -__logf(v + 1e-10f);
}

__device__ __forceinline__ void cap_push(float g, Scratch* sc) {
    if (g >= T1) {
        int p = atomicAdd(&sc->ccnt, 1);
        if (p < CAP) sc->cbuf[p] = g;
    }
}

__global__ void __launch_bounds__(NT, 1)
gumbel_sampler_kernel(const float* __restrict__ logits,
                      const float* __restrict__ uin,
                      const int* __restrict__ kp,
                      float* __restrict__ out)
{
    extern __shared__ unsigned char smem_raw[];
    float2*  gs2 = (float2*)smem_raw;
    float*   gsf = (float*)smem_raw;            // pairs + scalar as 50257 floats
    Scratch* sc  = (Scratch*)(smem_raw + GS_BYTES);

    const int row = blockIdx.x;
    const int tid = threadIdx.x;
    const int p   = row & 1;                    // peel count for 8B alignment
    const int esc = p ? 0 : (VOCAB - 1);        // global index of the scalar element
    const float* __restrict__ lrow = logits + (size_t)row * VOCAB;
    const float* __restrict__ urow = uin    + (size_t)row * VOCAB;
    float* __restrict__ orow = out + (size_t)row * VOCAB;
    const float2* __restrict__ l2 = (const float2*)(lrow + p);
    const float2* __restrict__ u2 = (const float2*)(urow + p);
    float2* __restrict__ o2 = (float2*)(orow + p);
    const int k = *kp;

    if (tid == 0) sc->ccnt = 0;
    __syncthreads();

    float2 lreg2[NPJ + 1];

    // ------- P1: vectorized load + gumbel; g -> smem; capture g>=T1 -------
    // FULL unroll is load-bearing: lreg2[] must stay in registers (partial unroll
    // demotes it to local memory -> 2x regression, see R3 post-mortem).
    #pragma unroll
    for (int j = 0; j < NPJ; ++j) {
        int t = tid + j * NT;
        float2 lv = __ldcs(l2 + t);
        float2 uv = __ldcs(u2 + t);
        float gx = lv.x + gumbel_noise(uv.x);
        float gy = lv.y + gumbel_noise(uv.y);
        lreg2[j] = lv;
        gs2[t] = make_float2(gx, gy);
        cap_push(gx, sc);
        cap_push(gy, sc);
    }
    if (tid < TAILP) {
        int t = NPJ * NT + tid;
        float2 lv = __ldcs(l2 + t);
        float2 uv = __ldcs(u2 + t);
        float gx = lv.x + gumbel_noise(uv.x);
        float gy = lv.y + gumbel_noise(uv.y);
        lreg2[NPJ] = lv;
        gs2[t] = make_float2(gx, gy);
        cap_push(gx, sc);
        cap_push(gy, sc);
    }
    if (tid == 0) {   // peeled scalar element
        float l = __ldcs(lrow + esc);
        float g = l + gumbel_noise(__ldcs(urow + esc));
        gsf[2 * NPAIR] = g;
        sc->lscalar = l;
        cap_push(g, sc);
    }
    __syncthreads();

    // ------- L2 prefetch of the next wave's row, EARLY (post-P1) -------
    // The whole P2+P3 window lets the prefetch drain from DRAM into L2 before
    // the next CTA on this SM reads these lines in its P1. Late placement
    // regressed 383->400us in R7: not enough drain time.
    {
        int pf = row + 148;
        if (pf < (int)gridDim.x) {
            const float* pl = logits + (size_t)pf * VOCAB;
            const float* pu = uin    + (size_t)pf * VOCAB;
            #pragma unroll 1
            for (int i = tid * 32; i < VOCAB; i += NT * 32) {
                asm volatile("prefetch.global.L2 [%0];" :: "l"(pl + i));
                asm volatile("prefetch.global.L2 [%0];" :: "l"(pu + i));
            }
        }
    }

    // ------- P2: exact k-th largest directly from the candidate buffer -------
    // count(>=T1) = m >= k  =>  k-th largest overall is the k-th largest of cbuf.
    int m = sc->ccnt;
    float thr;

    if (m >= k && m <= 512) {
        if (tid < m) {
            float vt = sc->cbuf[tid];
            int gt = 0, ge = 0;
            for (int j = 0; j < m; ++j) {
                float vj = sc->cbuf[j];         // broadcast LDS
                gt += (vj >  vt);
                ge += (vj >= vt);
            }
            if (gt < k && k <= ge) sc->thrslot = vt;
        }
        __syncthreads();
        thr = sc->thrslot;
    } else {
        // fallback (never expected): full bisection over all 50257 g values
        unsigned lo = 0u, hi = 0xFFFFFFFFu;
        int c_lo = VOCAB, c_hi = 0;
        while ((hi - lo) > 1u && (c_lo - c_hi) > WMAX) {
            unsigned mid = lo + ((hi - lo) >> 1);
            int c = 0;
            for (int i = tid; i < VOCAB; i += NT) c += (fkey(gsf[i]) >= mid);
            c = blockSumI(c, sc->sredi);
            if (c >= k) { lo = mid; c_lo = c; }
            else        { hi = mid; c_hi = c; }
        }
        if ((hi - lo) <= 1u) {
            thr = keyf(lo);
        } else {
            if (tid == 0) sc->wcnt = 0;
            __syncthreads();
            for (int i = tid; i < VOCAB; i += NT) {
                float v = gsf[i];
                unsigned kk = fkey(v);
                if (kk >= lo && kk < hi) {
                    int pq = atomicAdd(&sc->wcnt, 1);
                    if (pq < WMAX + 32) sc->wbuf[pq] = v;
                }
            }
            __syncthreads();
            int w = sc->wcnt; if (w > WMAX + 32) w = WMAX + 32;
            int need = k - c_hi;
            if (tid < w) {
                float vt = sc->wbuf[tid];
                int gt = 0, ge = 0;
                for (int j = 0; j < w; ++j) {
                    float vj = sc->wbuf[j];
                    gt += (vj >  vt);
                    ge += (vj >= vt);
                }
                if (gt < need && need <= ge) sc->thrslot = vt;
            }
            __syncthreads();
            thr = sc->thrslot;
        }
    }

    // ------- P3: fused mask + exp + sum (single pass; no max subtraction) -------
    // masked = l * sigmoid(g - thr) is bounded by |l| <= ~5.5 for N(0,1) inputs,
    // so exp(masked) is in [e^-6, e^6]: no fp32 overflow/underflow possible,
    // and softmax without max-shift is exact.
    float lsum = 0.0f;
    #pragma unroll
    for (int j = 0; j < NPJ; ++j) {
        int t = tid + j * NT;
        float2 g = gs2[t];
        float sx = __fdividef(1.0f, 1.0f + __expf(thr - g.x));
        float sy = __fdividef(1.0f, 1.0f + __expf(thr - g.y));
        float ex = __expf(lreg2[j].x * sx);
        float ey = __expf(lreg2[j].y * sy);
        lreg2[j] = make_float2(ex, ey);
        lsum += ex + ey;
    }
    if (tid < TAILP) {
        int t = NPJ * NT + tid;
        float2 g = gs2[t];
        float sx = __fdividef(1.0f, 1.0f + __expf(thr - g.x));
        float sy = __fdividef(1.0f, 1.0f + __expf(thr - g.y));
        float ex = __expf(lreg2[NPJ].x * sx);
        float ey = __expf(lreg2[NPJ].y * sy);
        lreg2[NPJ] = make_float2(ex, ey);
        lsum += ex + ey;
    }
    if (tid == 0) {
        float g = gsf[2 * NPAIR];
        float s = __fdividef(1.0f, 1.0f + __expf(thr - g));
        float e = __expf(sc->lscalar * s);
        sc->escalar = e;
        lsum += e;
    }
    float S = blockSumF(lsum, sc->sredf);
    float inv = __fdividef(1.0f, S);

    // ------- Pass C: scaled streaming vector stores straight from registers -------
    #pragma unroll
    for (int j = 0; j < NPJ; ++j) {
        int t = tid + j * NT;
        __stcs(o2 + t, make_float2(lreg2[j].x * inv, lreg2[j].y * inv));
    }
    if (tid < TAILP) {
        int t = NPJ * NT + tid;
        __stcs(o2 + t, make_float2(lreg2[NPJ].x * inv, lreg2[NPJ].y * inv));
    }
    if (tid == 0) {
        __stcs(orow + esc, sc->escalar * inv);
    }
}

extern "C" void kernel_launch(void* const* d_in, const int* in_sizes, int n_in,
                              void* d_out, int out_size)
{
    const float* logits = (const float*)d_in[0];
    const float* u      = (const float*)d_in[1];
    const int*   kp     = (const int*)d_in[2];
    float* out = (float*)d_out;

    int B = out_size / VOCAB;

    cudaFuncSetAttribute(gumbel_sampler_kernel,
                         cudaFuncAttributeMaxDynamicSharedMemorySize, SMEM_TOTAL);
    gumbel_sampler_kernel<<<B, NT, SMEM_TOTAL>>>(logits, u, kp, out);
}

// round 10
// speedup vs baseline: 1.2285x; 1.0425x over previous
#include <cuda_runtime.h>

#define VOCAB 50257
#define NT 1024
#define NW 32                    // warps per block
#define NPAIR 25128              // float2 pairs per row after 1-element peel
#define NPJ 24                   // full pair iterations: 24*1024 = 24576
#define TAILP 552                // tail pairs: 25128 - 24576
#define T1 6.0f                  // capture threshold; E[count(g>=6)] ~ 205, k-th ~ 7.4
#define CAP 768                  // candidate buffer capacity (mean 205, sigma ~14)
#define WMAX 128                 // fallback bisection window
// pairs [0..25127] then scalar slot at float index 50256 -> contiguous 50257 floats
#define GS_BYTES ((NPAIR * 8 + 4 + 15) & ~15)

#define NEG_SENT -3.402823466e38f

struct Scratch {
    int      sredi[NW + 1];
    float    sredf[NW + 1];
    float    cbuf[CAP];
    float    wbuf[WMAX + 32];
    int      ccnt;
    int      wcnt;
    float    thrslot;
    float    lscalar;            // logit of the peeled scalar element
    float    escalar;            // its exp value
};

#define SMEM_TOTAL (GS_BYTES + (int)sizeof(Scratch))

// ---- order-preserving float <-> u32 key (fallback path only) ----
__device__ __forceinline__ unsigned fkey(float f) {
    unsigned b = __float_as_uint(f);
    unsigned m = (unsigned)(((int)b) >> 31) | 0x80000000u;
    return b ^ m;
}
__device__ __forceinline__ float keyf(unsigned k) {
    unsigned m = (~(unsigned)(((int)k) >> 31)) | 0x80000000u;
    return __uint_as_float(k ^ m);
}

// ---- block reductions (1024 threads = 32 warps) ----
__device__ __forceinline__ int blockSumI(int v, int* s) {
    #pragma unroll
    for (int o = 16; o; o >>= 1) v += __shfl_xor_sync(0xffffffffu, v, o);
    int wid = threadIdx.x >> 5, lane = threadIdx.x & 31;
    if (lane == 0) s[wid] = v;
    __syncthreads();
    if (wid == 0) {
        int x = s[lane];
        #pragma unroll
        for (int o = 16; o; o >>= 1) x += __shfl_xor_sync(0xffffffffu, x, o);
        if (lane == 0) s[NW] = x;
    }
    __syncthreads();
    int r = s[NW];
    __syncthreads();
    return r;
}

__device__ __forceinline__ float blockSumF(float v, float* s) {
    #pragma unroll
    for (int o = 16; o; o >>= 1) v += __shfl_xor_sync(0xffffffffu, v, o);
    int wid = threadIdx.x >> 5, lane = threadIdx.x & 31;
    if (lane == 0) s[wid] = v;
    __syncthreads();
    if (wid == 0) {
        float x = s[lane];
        #pragma unroll
        for (int o = 16; o; o >>= 1) x += __shfl_xor_sync(0xffffffffu, x, o);
        if (lane == 0) s[NW] = x;
    }
    __syncthreads();
    float r = s[NW];
    __syncthreads();
    return r;
}

// noise = -log(-log(u + EPS) + EPS), with an exact log1p polynomial for u near 1
// (u -> 1 is exactly the top-k-defining region; MUFU LG2's absolute error there
//  would otherwise amplify to ~1e-2 in the noise).
__device__ __forceinline__ float gumbel_noise(float uu) {
    float vlog = -__logf(uu + 1e-10f);
    float d = uu - 1.0f;                         // exact (Sterbenz) for uu in [0.5, 2)
    float p = __fmaf_rn(-0.25f, d, 0.33333333f); // log1p(d) = d*(1 - d/2 + d^2/3 - d^3/4)
    p = __fmaf_rn(p, d, -0.5f);
    p = __fmaf_rn(p, d, 1.0f);
    float vpoly = -(d * p);
    float v = (uu > 0.99f) ? vpoly : vlog;
    return -__logf(v + 1e-10f);
}

__device__ __forceinline__ void cap_push(float g, Scratch* sc) {
    if (g >= T1) {
        int p = atomicAdd(&sc->ccnt, 1);
        if (p < CAP) sc->cbuf[p] = g;
    }
}

__global__ void __launch_bounds__(NT, 1)
gumbel_sampler_kernel(const float* __restrict__ logits,
                      const float* __restrict__ uin,
                      const int* __restrict__ kp,
                      float* __restrict__ out)
{
    extern __shared__ unsigned char smem_raw[];
    float2*  gs2 = (float2*)smem_raw;
    float*   gsf = (float*)smem_raw;            // pairs + scalar as 50257 floats
    Scratch* sc  = (Scratch*)(smem_raw + GS_BYTES);

    const int row = blockIdx.x;
    const int tid = threadIdx.x;
    const int p   = row & 1;                    // peel count for 8B alignment
    const int esc = p ? 0 : (VOCAB - 1);        // global index of the scalar element
    const float* __restrict__ lrow = logits + (size_t)row * VOCAB;
    const float* __restrict__ urow = uin    + (size_t)row * VOCAB;
    float* __restrict__ orow = out + (size_t)row * VOCAB;
    const float2* __restrict__ l2 = (const float2*)(lrow + p);
    const float2* __restrict__ u2 = (const float2*)(urow + p);
    float2* __restrict__ o2 = (float2*)(orow + p);

    if (tid == 0) sc->ccnt = 0;
    __syncthreads();

    float2 lreg2[NPJ + 1];

    // ------- P1: vectorized load + gumbel; g -> smem; capture g>=T1 -------
    // FULL unroll is load-bearing: lreg2[] must stay in registers (partial unroll
    // demotes it to local memory -> 2x regression, see R3 post-mortem).
    #pragma unroll
    for (int j = 0; j < NPJ; ++j) {
        int t = tid + j * NT;
        float2 lv = __ldcs(l2 + t);
        float2 uv = __ldcs(u2 + t);
        float gx = lv.x + gumbel_noise(uv.x);
        float gy = lv.y + gumbel_noise(uv.y);
        lreg2[j] = lv;
        gs2[t] = make_float2(gx, gy);
        cap_push(gx, sc);
        cap_push(gy, sc);
    }
    if (tid < TAILP) {
        int t = NPJ * NT + tid;
        float2 lv = __ldcs(l2 + t);
        float2 uv = __ldcs(u2 + t);
        float gx = lv.x + gumbel_noise(uv.x);
        float gy = lv.y + gumbel_noise(uv.y);
        lreg2[NPJ] = lv;
        gs2[t] = make_float2(gx, gy);
        cap_push(gx, sc);
        cap_push(gy, sc);
    }
    if (tid == 0) {   // peeled scalar element
        float l = __ldcs(lrow + esc);
        float g = l + gumbel_noise(__ldcs(urow + esc));
        gsf[2 * NPAIR] = g;
        sc->lscalar = l;
        cap_push(g, sc);
    }
    __syncthreads();

    // ------- L2 prefetch of the next wave's row, EARLY (post-P1) -------
    // The whole P2+P3 window lets the prefetch drain from DRAM into L2 before
    // the next CTA on this SM reads these lines in its P1. Late placement
    // regressed 383->400us in R7: not enough drain time.
    {
        int pf = row + 148;
        if (pf < (int)gridDim.x) {
            const float* pl = logits + (size_t)pf * VOCAB;
            const float* pu = uin    + (size_t)pf * VOCAB;
            #pragma unroll 1
            for (int i = tid * 32; i < VOCAB; i += NT * 32) {
                asm volatile("prefetch.global.L2 [%0];" :: "l"(pl + i));
                asm volatile("prefetch.global.L2 [%0];" :: "l"(pu + i));
            }
        }
    }

    // ------- P2: exact k-th largest directly from the candidate buffer -------
    // count(>=T1) = m >= k  =>  k-th largest overall is the k-th largest of cbuf.
    const int k = *kp;
    int m = sc->ccnt;
    float thr;

    if (m >= k && m <= CAP) {
        if (tid < m) {
            float vt = sc->cbuf[tid];
            int gt = 0, ge = 0;
            for (int j = 0; j < m; ++j) {
                float vj = sc->cbuf[j];         // broadcast LDS
                gt += (vj >  vt);
                ge += (vj >= vt);
            }
            if (gt < k && k <= ge) sc->thrslot = vt;
        }
        __syncthreads();
        thr = sc->thrslot;
    } else {
        // fallback (never expected): full bisection over all 50257 g values
        unsigned lo = 0u, hi = 0xFFFFFFFFu;
        int c_lo = VOCAB, c_hi = 0;
        while ((hi - lo) > 1u && (c_lo - c_hi) > WMAX) {
            unsigned mid = lo + ((hi - lo) >> 1);
            int c = 0;
            for (int i = tid; i < VOCAB; i += NT) c += (fkey(gsf[i]) >= mid);
            c = blockSumI(c, sc->sredi);
            if (c >= k) { lo = mid; c_lo = c; }
            else        { hi = mid; c_hi = c; }
        }
        if ((hi - lo) <= 1u) {
            thr = keyf(lo);
        } else {
            if (tid == 0) sc->wcnt = 0;
            __syncthreads();
            for (int i = tid; i < VOCAB; i += NT) {
                float v = gsf[i];
                unsigned kk = fkey(v);
                if (kk >= lo && kk < hi) {
                    int pq = atomicAdd(&sc->wcnt, 1);
                    if (pq < WMAX + 32) sc->wbuf[pq] = v;
                }
            }
            __syncthreads();
            int w = sc->wcnt; if (w > WMAX + 32) w = WMAX + 32;
            int need = k - c_hi;
            if (tid < w) {
                float vt = sc->wbuf[tid];
                int gt = 0, ge = 0;
                for (int j = 0; j < w; ++j) {
                    float vj = sc->wbuf[j];
                    gt += (vj >  vt);
                    ge += (vj >= vt);
                }
                if (gt < need && need <= ge) sc->thrslot = vt;
            }
            __syncthreads();
            thr = sc->thrslot;
        }
    }

    // ------- P3: fused mask + exp + sum (single pass; no max subtraction) -------
    // masked = l * sigmoid(g - thr) is bounded by |l| <= ~5.5 for N(0,1) inputs,
    // so exp(masked) is in [e^-6, e^6]: no fp32 overflow/underflow possible,
    // and softmax without max-shift is exact.
    float lsum = 0.0f;
    #pragma unroll
    for (int j = 0; j < NPJ; ++j) {
        int t = tid + j * NT;
        float2 g = gs2[t];
        float sx = __fdividef(1.0f, 1.0f + __expf(thr - g.x));
        float sy = __fdividef(1.0f, 1.0f + __expf(thr - g.y));
        float ex = __expf(lreg2[j].x * sx);
        float ey = __expf(lreg2[j].y * sy);
        lreg2[j] = make_float2(ex, ey);
        lsum += ex + ey;
    }
    if (tid < TAILP) {
        int t = NPJ * NT + tid;
        float2 g = gs2[t];
        float sx = __fdividef(1.0f, 1.0f + __expf(thr - g.x));
        float sy = __fdividef(1.0f, 1.0f + __expf(thr - g.y));
        float ex = __expf(lreg2[NPJ].x * sx);
        float ey = __expf(lreg2[NPJ].y * sy);
        lreg2[NPJ] = make_float2(ex, ey);
        lsum += ex + ey;
    }
    if (tid == 0) {
        float g = gsf[2 * NPAIR];
        float s = __fdividef(1.0f, 1.0f + __expf(thr - g));
        float e = __expf(sc->lscalar * s);
        sc->escalar = e;
        lsum += e;
    }
    float S = blockSumF(lsum, sc->sredf);
    float inv = __fdividef(1.0f, S);

    // ------- Pass C: scaled streaming vector stores straight from registers -------
    #pragma unroll
    for (int j = 0; j < NPJ; ++j) {
        int t = tid + j * NT;
        __stcs(o2 + t, make_float2(lreg2[j].x * inv, lreg2[j].y * inv));
    }
    if (tid < TAILP) {
        int t = NPJ * NT + tid;
        __stcs(o2 + t, make_float2(lreg2[NPJ].x * inv, lreg2[NPJ].y * inv));
    }
    if (tid == 0) {
        __stcs(orow + esc, sc->escalar * inv);
    }
}

extern "C" void kernel_launch(void* const* d_in, const int* in_sizes, int n_in,
                              void* d_out, int out_size)
{
    const float* logits = (const float*)d_in[0];
    const float* u      = (const float*)d_in[1];
    const int*   kp     = (const int*)d_in[2];
    float* out = (float*)d_out;

    int B = out_size / VOCAB;

    cudaFuncSetAttribute(gumbel_sampler_kernel,
                         cudaFuncAttributeMaxDynamicSharedMemorySize, SMEM_TOTAL);
    gumbel_sampler_kernel<<<B, NT, SMEM_TOTAL>>>(logits, u, kp, out);
}